// round 3
// baseline (speedup 1.0000x reference)
#include <cuda_runtime.h>
#include <cuda_bf16.h>

// GCN 2-layer: N=100000 nodes, E=1600000 edges, 64 features.
// CSR (dst-bucketed) built once with int atomics; per layer: smem GEMM ->
// pull aggregation (warp/node, register accum, no fp32 atomics).
// edge_index dtype (int32 vs int64) is detected at runtime (JAX x64 trap).

#define NN 100000
#define EE 1600000
#define FD 64
#define SCAN_TILE 1024
#define NBLK_SCAN ((NN + SCAN_TILE - 1) / SCAN_TILE)   // 98

// -------- device scratch --------
__device__ int   g_is64;
__device__ int   g_cnt[NN];
__device__ int   g_cursor[NN];
__device__ float g_dinv[NN];
__device__ int   g_rowptr[NN + 1];
__device__ int   g_bsums[NBLK_SCAN + 1];
__device__ int   g_esrc[EE];
__device__ float g_enorm[EE];
__device__ float g_h[NN * FD];    // x @ W1
__device__ float g_a[NN * FD];    // layer-1 aggregated + relu
__device__ float g_h2[NN * FD];   // g_a @ W2

// read edge index element `pos` with runtime dtype
__device__ __forceinline__ int edge_at(const int* __restrict__ ei,
                                       long long pos, int is64) {
    if (is64) return (int)((const long long* __restrict__)ei)[pos];
    return ei[pos];
}

// -------- dtype detection: int64 values <2^31 have all-zero odd words ----
__global__ void k_detect(const int* __restrict__ ei) {
    if (threadIdx.x == 0 && blockIdx.x == 0) {
        int any = 0;
        for (int i = 1; i < 512; i += 2) any |= ei[i];
        g_is64 = (any == 0) ? 1 : 0;
    }
}

// -------- graph preprocessing --------
__global__ void k_init(int n) {
    int i = blockIdx.x * blockDim.x + threadIdx.x;
    if (i < n) { g_cnt[i] = 0; g_cursor[i] = 0; }
}

__global__ void k_count_dst(const int* __restrict__ ei, int E) {
    int e = blockIdx.x * blockDim.x + threadIdx.x;
    if (e >= E) return;
    int is64 = g_is64;
    int d = edge_at(ei, (long long)E + e, is64);
    if ((unsigned)d < (unsigned)NN) atomicAdd(&g_cnt[d], 1);
}

__global__ void k_dinv(int n) {
    int i = blockIdx.x * blockDim.x + threadIdx.x;
    if (i < n) g_dinv[i] = rsqrtf((float)(g_cnt[i] + 1));  // +1 self-loop
}

__global__ void k_scan_block(int n) {   // grid=NBLK_SCAN, block=1024
    __shared__ int s[SCAN_TILE];
    int t = threadIdx.x;
    int gid = blockIdx.x * SCAN_TILE + t;
    int v = (gid < n) ? g_cnt[gid] : 0;
    s[t] = v;
    __syncthreads();
    #pragma unroll
    for (int off = 1; off < SCAN_TILE; off <<= 1) {
        int a = (t >= off) ? s[t - off] : 0;
        __syncthreads();
        s[t] += a;
        __syncthreads();
    }
    if (gid < n) g_rowptr[gid] = s[t] - v;     // exclusive scan
    if (t == SCAN_TILE - 1) g_bsums[blockIdx.x] = s[t];
}

__global__ void k_scan_sums(int nb) {   // <<<1,1>>>, nb=98 trivial
    int acc = 0;
    for (int i = 0; i < nb; i++) { int v = g_bsums[i]; g_bsums[i] = acc; acc += v; }
}

__global__ void k_add_sums(int n, int E) {
    int gid = blockIdx.x * blockDim.x + threadIdx.x;
    if (gid < n) g_rowptr[gid] += g_bsums[gid >> 10];
    if (gid == 0) g_rowptr[n] = E;
}

__global__ void k_fill_edges(const int* __restrict__ ei, int E) {
    int e = blockIdx.x * blockDim.x + threadIdx.x;
    if (e >= E) return;
    int is64 = g_is64;
    int s = edge_at(ei, e, is64);
    int d = edge_at(ei, (long long)E + e, is64);
    if ((unsigned)s >= (unsigned)NN || (unsigned)d >= (unsigned)NN) return;
    float nm = g_dinv[s] * g_dinv[d];
    int pos = g_rowptr[d] + atomicAdd(&g_cursor[d], 1);
    g_esrc[pos] = s;
    g_enorm[pos] = nm;
}

// -------- GEMM: H[n,64] = X[n,64] @ W[64,64], 64 rows per block --------
template <int LAYER>
__global__ __launch_bounds__(256) void k_gemm64(
    const float* __restrict__ Xin, const float* __restrict__ W, int n)
{
    const float* __restrict__ X = (LAYER == 0) ? Xin : (const float*)g_a;
    float* __restrict__ H = (LAYER == 0) ? g_h : g_h2;

    __shared__ float sW[FD][FD];
    __shared__ float sX[FD][FD];
    int t = threadIdx.x;
    int row0 = blockIdx.x * FD;
    for (int i = t; i < FD * FD; i += 256) sW[i >> 6][i & 63] = W[i];
    for (int i = t; i < FD * FD; i += 256) {
        int r = i >> 6, c = i & 63;
        sX[r][c] = (row0 + r < n) ? X[(size_t)(row0 + r) * FD + c] : 0.0f;
    }
    __syncthreads();

    int cg = (t & 15) * 4;   // 16 col-groups of 4
    int rg = (t >> 4) * 4;   // 16 row-groups of 4
    float acc[4][4] = {};
    #pragma unroll
    for (int k = 0; k < FD; k++) {
        float4 wv = *(const float4*)&sW[k][cg];
        #pragma unroll
        for (int i = 0; i < 4; i++) {
            float xv = sX[rg + i][k];
            acc[i][0] = fmaf(xv, wv.x, acc[i][0]);
            acc[i][1] = fmaf(xv, wv.y, acc[i][1]);
            acc[i][2] = fmaf(xv, wv.z, acc[i][2]);
            acc[i][3] = fmaf(xv, wv.w, acc[i][3]);
        }
    }
    #pragma unroll
    for (int i = 0; i < 4; i++) {
        int r = row0 + rg + i;
        if (r < n)
            *(float4*)&H[(size_t)r * FD + cg] =
                make_float4(acc[i][0], acc[i][1], acc[i][2], acc[i][3]);
    }
}

// -------- pull aggregation: warp per node, float2 per lane --------
template <int LAYER>
__global__ __launch_bounds__(256) void k_aggregate(
    const float* __restrict__ b, float* __restrict__ outp, int n)
{
    int warp = (blockIdx.x * blockDim.x + threadIdx.x) >> 5;
    int lane = threadIdx.x & 31;
    if (warp >= n) return;
    int i = warp;

    const float2* __restrict__ H2 =
        (LAYER == 0) ? (const float2*)g_h : (const float2*)g_h2;
    float2* __restrict__ O2 =
        (LAYER == 0) ? (float2*)g_a : (float2*)outp;

    float2 bb = ((const float2*)b)[lane];
    float  di = g_dinv[i];
    float  w  = di * di;                       // self-loop norm
    float2 hs = H2[(size_t)i * 32 + lane];
    float2 acc;
    acc.x = fmaf(hs.x, w, bb.x);
    acc.y = fmaf(hs.y, w, bb.y);

    int e0 = g_rowptr[i], e1 = g_rowptr[i + 1];
    #pragma unroll 2
    for (int e = e0; e < e1; e++) {
        int   s  = g_esrc[e];
        float nm = g_enorm[e];
        float2 hv = H2[(size_t)s * 32 + lane];
        acc.x = fmaf(hv.x, nm, acc.x);
        acc.y = fmaf(hv.y, nm, acc.y);
    }
    if (LAYER == 0) { acc.x = fmaxf(acc.x, 0.0f); acc.y = fmaxf(acc.y, 0.0f); }
    O2[(size_t)i * 32 + lane] = acc;
}

// -------- host launch (kernel launches ONLY) --------
extern "C" void kernel_launch(void* const* d_in, const int* in_sizes, int n_in,
                              void* d_out, int out_size)
{
    const float* x  = (const float*)d_in[0];
    const int*   ei = (const int*)d_in[1];     // dtype resolved on device
    const float* W1 = (const float*)d_in[2];
    const float* b1 = (const float*)d_in[3];
    const float* W2 = (const float*)d_in[4];
    const float* b2 = (const float*)d_in[5];
    float* out = (float*)d_out;

    int n = in_sizes[0] / FD;      // 100000
    int E = in_sizes[1] / 2;       // 1600000

    int tb = 256;
    int gN  = (n + tb - 1) / tb;
    int gE  = (E + tb - 1) / tb;
    int gG  = (n + FD - 1) / FD;               // gemm blocks (64 rows each)
    int gAg = (n * 32 + tb - 1) / tb;          // warp per node

    // CSR build (once, reused by both layers)
    k_detect<<<1, 32>>>(ei);
    k_init<<<gN, tb>>>(n);
    k_count_dst<<<gE, tb>>>(ei, E);
    k_dinv<<<gN, tb>>>(n);
    k_scan_block<<<NBLK_SCAN, SCAN_TILE>>>(n);
    k_scan_sums<<<1, 1>>>(NBLK_SCAN);
    k_add_sums<<<gN, tb>>>(n, E);
    k_fill_edges<<<gE, tb>>>(ei, E);

    // Layer 1
    k_gemm64<0><<<gG, 256>>>(x, W1, n);
    k_aggregate<0><<<gAg, 256>>>(b1, nullptr, n);

    // Layer 2
    k_gemm64<1><<<gG, 256>>>(nullptr, W2, n);
    k_aggregate<1><<<gAg, 256>>>(b2, out, n);
}

// round 4
// speedup vs baseline: 1.1440x; 1.1440x over previous
#include <cuda_runtime.h>
#include <cuda_bf16.h>

// GCN 2-layer: N=100000, E=1600000, 64 features.
// CSR (dst-bucketed) built once; per layer: f32x2-packed GEMM -> pull
// aggregation (warp/node, int2 edge payload, MLP-4 gathers, fp32 accum).

#define NN 100000
#define EE 1600000
#define FD 64
#define SCAN_TILE 1024
#define NBLK_SCAN ((NN + SCAN_TILE - 1) / SCAN_TILE)   // 98

typedef unsigned long long ull;

// -------- device scratch --------
__device__ int   g_is64;
__device__ int   g_cnt[NN];
__device__ int   g_cursor[NN];
__device__ float g_dinv[NN];
__device__ int   g_rowptr[NN + 1];
__device__ int   g_bsums[NBLK_SCAN];
__device__ int2  g_epay[EE];      // {src, float_bits(norm)}
__device__ float g_h[NN * FD];    // x @ W1
__device__ float g_a[NN * FD];    // relu(agg(h)) + b1
__device__ float g_h2[NN * FD];   // g_a @ W2

__device__ __forceinline__ int edge_at(const int* __restrict__ ei,
                                       long long pos, int is64) {
    if (is64) return (int)((const long long* __restrict__)ei)[pos];
    return ei[pos];
}

__device__ __forceinline__ void fma2(ull& d, ull a, ull b) {
    asm("fma.rn.f32x2 %0, %1, %2, %0;" : "+l"(d) : "l"(a), "l"(b));
}

// -------- init + dtype detection (int64 vals <2^31 -> odd words zero) ----
__global__ void k_init_detect(const int* __restrict__ ei, int n) {
    int i = blockIdx.x * blockDim.x + threadIdx.x;
    if (i < n) { g_cnt[i] = 0; g_cursor[i] = 0; }
    if (i == 0) {
        int any = 0;
        for (int j = 1; j < 512; j += 2) any |= ei[j];
        g_is64 = (any == 0) ? 1 : 0;
    }
}

__global__ void k_count_dst(const int* __restrict__ ei, int E) {
    int e = blockIdx.x * blockDim.x + threadIdx.x;
    if (e >= E) return;
    int d = edge_at(ei, (long long)E + e, g_is64);
    if ((unsigned)d < (unsigned)NN) atomicAdd(&g_cnt[d], 1);
}

// -------- block scan over counts; also emits dinv --------
__global__ void k_scan_block(int n) {   // grid=NBLK_SCAN, block=1024
    __shared__ int s[SCAN_TILE];
    int t = threadIdx.x;
    int gid = blockIdx.x * SCAN_TILE + t;
    int v = (gid < n) ? g_cnt[gid] : 0;
    if (gid < n) g_dinv[gid] = rsqrtf((float)(v + 1));  // +1 self-loop
    s[t] = v;
    __syncthreads();
    #pragma unroll
    for (int off = 1; off < SCAN_TILE; off <<= 1) {
        int a = (t >= off) ? s[t - off] : 0;
        __syncthreads();
        s[t] += a;
        __syncthreads();
    }
    if (gid < n) g_rowptr[gid] = s[t] - v;     // exclusive within block
    if (t == SCAN_TILE - 1) g_bsums[blockIdx.x] = s[t];
}

__global__ void k_scan_sums() {   // 1 block, 128 threads, 98 values
    __shared__ int s[128];
    int t = threadIdx.x;
    int v = (t < NBLK_SCAN) ? g_bsums[t] : 0;
    s[t] = v;
    __syncthreads();
    #pragma unroll
    for (int off = 1; off < 128; off <<= 1) {
        int a = (t >= off) ? s[t - off] : 0;
        __syncthreads();
        s[t] += a;
        __syncthreads();
    }
    if (t < NBLK_SCAN) g_bsums[t] = s[t] - v;  // exclusive
}

__global__ void k_add_sums(int n, int E) {
    int gid = blockIdx.x * blockDim.x + threadIdx.x;
    if (gid < n) g_rowptr[gid] += g_bsums[gid >> 10];
    if (gid == 0) g_rowptr[n] = E;
}

__global__ void k_fill_edges(const int* __restrict__ ei, int E) {
    int e = blockIdx.x * blockDim.x + threadIdx.x;
    if (e >= E) return;
    int is64 = g_is64;
    int s = edge_at(ei, e, is64);
    int d = edge_at(ei, (long long)E + e, is64);
    if ((unsigned)s >= (unsigned)NN || (unsigned)d >= (unsigned)NN) return;
    float nm = g_dinv[s] * g_dinv[d];
    int pos = g_rowptr[d] + atomicAdd(&g_cursor[d], 1);
    g_epay[pos] = make_int2(s, __float_as_int(nm));
}

// -------- GEMM: H[n,64] = X[n,64] @ W[64,64] --------
// 64 rows/block, 64 threads, each thread 8 rows x 8 cols, f32x2 packed FMA.
template <int LAYER>
__global__ __launch_bounds__(64) void k_gemm(
    const float* __restrict__ Xin, const float* __restrict__ W, int n)
{
    const float* __restrict__ X = (LAYER == 0) ? Xin : (const float*)g_a;
    float* __restrict__ H = (LAYER == 0) ? g_h : g_h2;

    __shared__ float sX[FD][FD + 1];   // pad -> conflict-free row reads
    __shared__ float sW[FD][FD];
    int t = threadIdx.x;
    int row0 = blockIdx.x * FD;

    // load W (4096 floats; 16 float4 per thread)
    for (int i = t * 4; i < FD * FD; i += 64 * 4)
        *(float4*)&sW[i >> 6][i & 63] = *(const float4*)&W[i];
    // load X tile (scalar stores into padded smem)
    for (int i4 = t; i4 < (FD * FD) / 4; i4 += 64) {
        int r = i4 >> 4, c = (i4 & 15) * 4;
        float4 v = (row0 + r < n) ? *(const float4*)&X[(size_t)(row0 + r) * FD + c]
                                  : make_float4(0.f, 0.f, 0.f, 0.f);
        sX[r][c] = v.x; sX[r][c + 1] = v.y; sX[r][c + 2] = v.z; sX[r][c + 3] = v.w;
    }
    __syncthreads();

    int c0 = (t & 7) * 8;
    int r0 = (t >> 3) * 8;
    ull acc[8][4];
    #pragma unroll
    for (int i = 0; i < 8; i++)
        #pragma unroll
        for (int j = 0; j < 4; j++) acc[i][j] = 0ull;

    #pragma unroll
    for (int k = 0; k < FD; k++) {
        union { float4 f; ull u[2]; } wa, wb;
        wa.f = *(const float4*)&sW[k][c0];
        wb.f = *(const float4*)&sW[k][c0 + 4];
        ull w0 = wa.u[0], w1 = wa.u[1], w2 = wb.u[0], w3 = wb.u[1];
        #pragma unroll
        for (int i = 0; i < 8; i++) {
            float xv = sX[r0 + i][k];
            ull xp;
            asm("mov.b64 %0, {%1, %1};" : "=l"(xp) : "f"(xv));
            fma2(acc[i][0], xp, w0);
            fma2(acc[i][1], xp, w1);
            fma2(acc[i][2], xp, w2);
            fma2(acc[i][3], xp, w3);
        }
    }

    #pragma unroll
    for (int i = 0; i < 8; i++) {
        int r = row0 + r0 + i;
        if (r < n) {
            union { float4 f; ull u[2]; } lo, hi;
            lo.u[0] = acc[i][0]; lo.u[1] = acc[i][1];
            hi.u[0] = acc[i][2]; hi.u[1] = acc[i][3];
            *(float4*)&H[(size_t)r * FD + c0]     = lo.f;
            *(float4*)&H[(size_t)r * FD + c0 + 4] = hi.f;
        }
    }
}

// -------- pull aggregation: warp per node, float2/lane, MLP-4 --------
template <int LAYER>
__global__ __launch_bounds__(256) void k_aggregate(
    const float* __restrict__ b, float* __restrict__ outp, int n)
{
    int node = (blockIdx.x * blockDim.x + threadIdx.x) >> 5;
    int lane = threadIdx.x & 31;
    if (node >= n) return;

    const float2* __restrict__ H2 =
        (LAYER == 0) ? (const float2*)g_h : (const float2*)g_h2;
    float2* __restrict__ O2 =
        (LAYER == 0) ? (float2*)g_a : (float2*)outp;

    float2 bb = ((const float2*)b)[lane];
    float  di = g_dinv[node];
    float  w  = di * di;                       // self-loop norm
    float2 hs = H2[(size_t)node * 32 + lane];
    float ax = fmaf(hs.x, w, bb.x);
    float ay = fmaf(hs.y, w, bb.y);

    int e  = g_rowptr[node];
    int e1 = g_rowptr[node + 1];
    for (; e + 4 <= e1; e += 4) {
        int2 p0 = g_epay[e];
        int2 p1 = g_epay[e + 1];
        int2 p2 = g_epay[e + 2];
        int2 p3 = g_epay[e + 3];
        float2 h0 = H2[(size_t)p0.x * 32 + lane];
        float2 h1 = H2[(size_t)p1.x * 32 + lane];
        float2 h2 = H2[(size_t)p2.x * 32 + lane];
        float2 h3 = H2[(size_t)p3.x * 32 + lane];
        float n0 = __int_as_float(p0.y), n1 = __int_as_float(p1.y);
        float n2 = __int_as_float(p2.y), n3 = __int_as_float(p3.y);
        ax = fmaf(h0.x, n0, ax); ay = fmaf(h0.y, n0, ay);
        ax = fmaf(h1.x, n1, ax); ay = fmaf(h1.y, n1, ay);
        ax = fmaf(h2.x, n2, ax); ay = fmaf(h2.y, n2, ay);
        ax = fmaf(h3.x, n3, ax); ay = fmaf(h3.y, n3, ay);
    }
    for (; e < e1; e++) {
        int2 p = g_epay[e];
        float2 hv = H2[(size_t)p.x * 32 + lane];
        float nm = __int_as_float(p.y);
        ax = fmaf(hv.x, nm, ax); ay = fmaf(hv.y, nm, ay);
    }
    if (LAYER == 0) { ax = fmaxf(ax, 0.0f); ay = fmaxf(ay, 0.0f); }
    O2[(size_t)node * 32 + lane] = make_float2(ax, ay);
}

// -------- host launch (kernel launches ONLY; graph-capture safe) --------
extern "C" void kernel_launch(void* const* d_in, const int* in_sizes, int n_in,
                              void* d_out, int out_size)
{
    const float* x  = (const float*)d_in[0];
    const int*   ei = (const int*)d_in[1];     // dtype resolved on device
    const float* W1 = (const float*)d_in[2];
    const float* b1 = (const float*)d_in[3];
    const float* W2 = (const float*)d_in[4];
    const float* b2 = (const float*)d_in[5];
    float* out = (float*)d_out;

    int n = in_sizes[0] / FD;      // 100000
    int E = in_sizes[1] / 2;       // 1600000

    int tb = 256;
    int gN  = (n + tb - 1) / tb;
    int gE  = (E + tb - 1) / tb;
    int gG  = (n + FD - 1) / FD;               // 64 rows per gemm block
    int gAg = (n * 32 + tb - 1) / tb;          // warp per node

    // CSR build (once, reused by both layers)
    k_init_detect<<<gN, tb>>>(ei, n);
    k_count_dst<<<gE, tb>>>(ei, E);
    k_scan_block<<<NBLK_SCAN, SCAN_TILE>>>(n);
    k_scan_sums<<<1, 128>>>();
    k_add_sums<<<gN, tb>>>(n, E);
    k_fill_edges<<<gE, tb>>>(ei, E);

    // Layer 1
    k_gemm<0><<<gG, 64>>>(x, W1, n);
    k_aggregate<0><<<gAg, 256>>>(b1, nullptr, n);

    // Layer 2
    k_gemm<1><<<gG, 64>>>(nullptr, W2, n);
    k_aggregate<1><<<gAg, 256>>>(b2, out, n);
}